// round 3
// baseline (speedup 1.0000x reference)
#include <cuda_runtime.h>

// Problem constants (fixed by the dataset): B=16384, F=256, T=512, D=7, C=4
#define N_FEATS     256
#define N_TREES     512
#define DEPTH       7
#define TOTAL_NODES 130048      // T * (2^(D+1) - 2)
#define MAX_B       16384

#define TPB             256
#define WARPS_PER_CTA   8
#define SAMPLES_PER_CTA 32
#define HALVES          2
#define TREES_PER_HALF  (N_TREES / HALVES)                 // 256
#define TREES_PER_WARP  (TREES_PER_HALF / WARPS_PER_CTA)   // 32
#define NT              8        // concurrent tree traversals per thread (ILP)

// Fused (feature_id, bias) table: one LDG.64 per level instead of two LDG.32.
__device__ int2 g_combined[TOTAL_NODES];
// x transposed to feature-major: g_xT[f * B + s]  (16 MB static scratch)
__device__ float g_xT[N_FEATS * MAX_B];
// Per-half partial sums (float4 per sample).
__device__ float4 g_part[HALVES * MAX_B];

// Fused prep: transpose x (B,256) -> xT (256,B) AND pack nodes+biases.
// Grid: (B/32) * (F/32) = 512*8 = 4096 blocks of 256 threads.
// Blocks 0..507 additionally pack one 256-entry chunk of the node table.
__global__ __launch_bounds__(TPB) void prep_kernel(
    const float* __restrict__ x,
    const int*   __restrict__ nodes,
    const float* __restrict__ biases,
    int B)
{
    __shared__ float tile[32][33];

    const int tid = threadIdx.x;
    const int tx  = tid & 31;
    const int ty  = tid >> 5;          // 0..7

    // Pack (covers TOTAL_NODES = 508*256 exactly).
    {
        int i = blockIdx.x * TPB + tid;
        if (i < TOTAL_NODES)
            g_combined[i] = make_int2(nodes[i], __float_as_int(biases[i]));
    }

    const int tb = blockIdx.x & 511;   // sample tile (B/32 = 512)
    const int tf = blockIdx.x >> 9;    // feature tile (F/32 = 8)

    #pragma unroll
    for (int k = 0; k < 4; k++) {
        int s = tb * 32 + ty + k * 8;
        int f = tf * 32 + tx;
        tile[ty + k * 8][tx] = x[s * N_FEATS + f];
    }
    __syncthreads();
    #pragma unroll
    for (int k = 0; k < 4; k++) {
        int f = tf * 32 + ty + k * 8;
        int s = tb * 32 + tx;
        g_xT[f * B + s] = tile[tx][ty + k * 8];
    }
}

__global__ __launch_bounds__(TPB) void tree_kernel(
    const int*    __restrict__ root_nodes,   // (T,)
    const float*  __restrict__ root_biases,  // (T,)
    const int*    __restrict__ tree_indices, // (T,) = 2*t
    const float4* __restrict__ leaf,         // (T*256, 4) as float4
    int B)
{
    // Feature-major x tile: xs[f*32 + local_sample]. Bank = local_sample
    // => conflict-free LDS for arbitrary per-lane feature indices.
    // Reused as the cross-warp reduction buffer after traversal.
    __shared__ float xs[N_FEATS * SAMPLES_PER_CTA];   // 32 KB

    const int tid  = threadIdx.x;
    const int lane = tid & 31;
    const int w    = tid >> 5;
    const int s0   = blockIdx.x * SAMPLES_PER_CTA;
    const int half = blockIdx.y;

    // Stage from xT: coalesced global reads, conflict-free smem writes.
    #pragma unroll
    for (int i = tid; i < N_FEATS * SAMPLES_PER_CTA; i += TPB) {
        int c = i >> 5;          // feature
        int r = i & 31;          // local sample
        xs[c * 32 + r] = g_xT[c * B + s0 + r];
    }
    __syncthreads();

    float a0 = 0.f, a1 = 0.f, a2 = 0.f, a3 = 0.f;
    const int tbase = half * TREES_PER_HALF + w * TREES_PER_WARP;

    for (int tt = 0; tt < TREES_PER_WARP; tt += NT) {
        int idx[NT];

        // Root level: uniform per-tree metadata (broadcast loads).
        #pragma unroll
        for (int j = 0; j < NT; j++) {
            int t = tbase + tt + j;
            int   rf = __ldg(&root_nodes[t]);
            float rb = __ldg(&root_biases[t]);
            int   ti = __ldg(&tree_indices[t]);
            idx[j] = ti + (xs[rf * 32 + lane] < rb ? 1 : 0);
        }

        // Levels 1..7: level-l block starts at T*(2^l - 2); idx is GLOBAL
        // within the level (matches reference).
        int off = 0;
        #pragma unroll
        for (int l = 1; l <= DEPTH; l++) {
            #pragma unroll
            for (int j = 0; j < NT; j++) {
                int2 e = __ldg(&g_combined[off + idx[j]]);        // LDG.64
                float f = xs[e.x * 32 + lane];                    // LDS, no conflicts
                idx[j] = 2 * idx[j] + (f < __int_as_float(e.y) ? 1 : 0);
            }
            off += N_TREES << l;
        }

        // Leaf accumulate (one LDG.128 per tree).
        #pragma unroll
        for (int j = 0; j < NT; j++) {
            float4 v = __ldg(&leaf[idx[j]]);
            a0 += v.x; a1 += v.y; a2 += v.z; a3 += v.w;
        }
    }

    // Deterministic cross-warp reduction, reusing xs as scratch.
    __syncthreads();                       // all warps done reading xs
    float* red = xs;                       // [warp][lane][4]
    red[(w * SAMPLES_PER_CTA + lane) * 4 + 0] = a0;
    red[(w * SAMPLES_PER_CTA + lane) * 4 + 1] = a1;
    red[(w * SAMPLES_PER_CTA + lane) * 4 + 2] = a2;
    red[(w * SAMPLES_PER_CTA + lane) * 4 + 3] = a3;
    __syncthreads();

    if (w == 0) {
        float4 r = make_float4(0.f, 0.f, 0.f, 0.f);
        #pragma unroll
        for (int ww = 0; ww < WARPS_PER_CTA; ww++) {
            const float* p = red + (ww * SAMPLES_PER_CTA + lane) * 4;
            r.x += p[0]; r.y += p[1]; r.z += p[2]; r.w += p[3];
        }
        g_part[half * B + s0 + lane] = r;
    }
}

__global__ void reduce_kernel(float4* __restrict__ out, int B) {
    int i = blockIdx.x * blockDim.x + threadIdx.x;
    if (i < B) {
        float4 a = g_part[i];
        float4 b = g_part[B + i];
        out[i] = make_float4(a.x + b.x, a.y + b.y, a.z + b.z, a.w + b.w);
    }
}

extern "C" void kernel_launch(void* const* d_in, const int* in_sizes, int n_in,
                              void* d_out, int out_size) {
    const float* x            = (const float*)d_in[0];
    const int*   root_nodes   = (const int*)  d_in[1];
    const float* root_biases  = (const float*)d_in[2];
    const int*   tree_indices = (const int*)  d_in[3];
    const int*   nodes_flat   = (const int*)  d_in[4];
    const float* biases_flat  = (const float*)d_in[5];
    const float4* leaf        = (const float4*)d_in[6];
    float4* out               = (float4*)d_out;

    const int B = in_sizes[0] / N_FEATS;   // 16384

    cudaFuncSetAttribute(tree_kernel,
                         cudaFuncAttributePreferredSharedMemoryCarveout, 100);

    prep_kernel<<<(B / 32) * (N_FEATS / 32), TPB>>>(x, nodes_flat, biases_flat, B);

    dim3 grid(B / SAMPLES_PER_CTA, HALVES);
    tree_kernel<<<grid, TPB>>>(root_nodes, root_biases, tree_indices, leaf, B);

    reduce_kernel<<<(B + TPB - 1) / TPB, TPB>>>(out, B);
}

// round 4
// speedup vs baseline: 1.0228x; 1.0228x over previous
#include <cuda_runtime.h>

// Problem constants (fixed by the dataset): B=16384, F=256, T=512, D=7, C=4
#define N_FEATS     256
#define N_TREES     512
#define DEPTH       7
#define TOTAL_NODES 130048      // T * (2^(D+1) - 2)
#define MAX_B       16384

#define TPB             256
#define WARPS_PER_CTA   8
#define SAMPLES_PER_CTA 32
#define HALVES          2
#define TREES_PER_HALF  (N_TREES / HALVES)                 // 256
#define TREES_PER_WARP  (TREES_PER_HALF / WARPS_PER_CTA)   // 32 == warp size
#define NT              8        // concurrent tree traversals per thread (ILP)

// Fused (feature_id, bias) table: one LDG.64 per level instead of two LDG.32.
__device__ int2 g_combined[TOTAL_NODES];
// Per-half partial sums (float4 per sample).
__device__ float4 g_part[HALVES * MAX_B];

__global__ void pack_kernel(const int* __restrict__ nodes,
                            const float* __restrict__ biases) {
    int i = blockIdx.x * blockDim.x + threadIdx.x;
    if (i < TOTAL_NODES) {
        g_combined[i] = make_int2(nodes[i], __float_as_int(biases[i]));
    }
}

__global__ __launch_bounds__(TPB) void tree_kernel(
    const float*  __restrict__ x,            // (B, 256) row-major
    const int*    __restrict__ root_nodes,   // (T,)
    const float*  __restrict__ root_biases,  // (T,)
    const int*    __restrict__ tree_indices, // (T,) = 2*t
    const float4* __restrict__ leaf,         // (T*256, 4) as float4
    int B)
{
    // Feature-major x tile: xs[f*32 + local_sample]. Bank = local_sample
    // => conflict-free LDS for arbitrary per-lane feature indices.
    // Reused as the cross-warp reduction buffer after traversal.
    __shared__ float xs[N_FEATS * SAMPLES_PER_CTA];   // 32 KB
    __shared__ float tmp[SAMPLES_PER_CTA][33];        // 4.2 KB transpose tile

    const int tid  = threadIdx.x;
    const int lane = tid & 31;
    const int w    = tid >> 5;
    const int s0   = blockIdx.x * SAMPLES_PER_CTA;
    const int half = blockIdx.y;

    // ---- In-CTA transpose staging: row-major gmem -> feature-major smem ----
    // Chunk of 32 features at a time through a padded tile; all gmem reads
    // coalesced, all smem accesses bank-conflict-free.
    {
        const int cA = tid & 31;       // feature within chunk (phase A)
        const int rA = tid >> 5;       // sample row base (phase A)
        #pragma unroll
        for (int cf = 0; cf < N_FEATS; cf += 32) {
            #pragma unroll
            for (int k = 0; k < 4; k++) {
                int r = rA + k * 8;
                // banks: (r*33 + cA) % 32 = (r + cA) % 32, distinct per warp
                tmp[r][cA] = x[(s0 + r) * N_FEATS + cf + cA];
            }
            __syncthreads();
            #pragma unroll
            for (int k = 0; k < 4; k++) {
                int c = w + k * 8;
                // read bank (lane*33 + c)%32 distinct; write bank = lane distinct
                xs[(cf + c) * 32 + lane] = tmp[lane][c];
            }
            __syncthreads();
        }
    }

    float a0 = 0.f, a1 = 0.f, a2 = 0.f, a3 = 0.f;
    const int tbase = half * TREES_PER_HALF + w * TREES_PER_WARP;

    // Per-warp root metadata: one tree per lane, broadcast later via shfl.
    const int   rn_l = __ldg(&root_nodes[tbase + lane]);
    const float rb_l = __ldg(&root_biases[tbase + lane]);
    const int   ti_l = __ldg(&tree_indices[tbase + lane]);

    for (int tt = 0; tt < TREES_PER_WARP; tt += NT) {
        int idx[NT];

        // Root level: per-tree metadata broadcast from lane registers.
        #pragma unroll
        for (int j = 0; j < NT; j++) {
            int   rf = __shfl_sync(0xffffffffu, rn_l, tt + j);
            float rb = __shfl_sync(0xffffffffu, rb_l, tt + j);
            int   ti = __shfl_sync(0xffffffffu, ti_l, tt + j);
            idx[j] = ti + (xs[rf * 32 + lane] < rb ? 1 : 0);
        }

        // Levels 1..7: level-l block starts at T*(2^l - 2); idx is GLOBAL
        // within the level (matches reference).
        int off = 0;
        #pragma unroll
        for (int l = 1; l <= DEPTH; l++) {
            #pragma unroll
            for (int j = 0; j < NT; j++) {
                int2 e = __ldg(&g_combined[off + idx[j]]);        // LDG.64
                float f = xs[e.x * 32 + lane];                    // LDS, no conflicts
                idx[j] = 2 * idx[j] + (f < __int_as_float(e.y) ? 1 : 0);
            }
            off += N_TREES << l;
        }

        // Leaf accumulate (one LDG.128 per tree).
        #pragma unroll
        for (int j = 0; j < NT; j++) {
            float4 v = __ldg(&leaf[idx[j]]);
            a0 += v.x; a1 += v.y; a2 += v.z; a3 += v.w;
        }
    }

    // Deterministic cross-warp reduction, reusing xs as scratch.
    __syncthreads();                       // all warps done reading xs
    float* red = xs;                       // [warp][lane][4]
    red[(w * SAMPLES_PER_CTA + lane) * 4 + 0] = a0;
    red[(w * SAMPLES_PER_CTA + lane) * 4 + 1] = a1;
    red[(w * SAMPLES_PER_CTA + lane) * 4 + 2] = a2;
    red[(w * SAMPLES_PER_CTA + lane) * 4 + 3] = a3;
    __syncthreads();

    if (w == 0) {
        float4 r = make_float4(0.f, 0.f, 0.f, 0.f);
        #pragma unroll
        for (int ww = 0; ww < WARPS_PER_CTA; ww++) {
            const float* p = red + (ww * SAMPLES_PER_CTA + lane) * 4;
            r.x += p[0]; r.y += p[1]; r.z += p[2]; r.w += p[3];
        }
        g_part[half * B + s0 + lane] = r;
    }
}

__global__ void reduce_kernel(float4* __restrict__ out, int B) {
    int i = blockIdx.x * blockDim.x + threadIdx.x;
    if (i < B) {
        float4 a = g_part[i];
        float4 b = g_part[B + i];
        out[i] = make_float4(a.x + b.x, a.y + b.y, a.z + b.z, a.w + b.w);
    }
}

extern "C" void kernel_launch(void* const* d_in, const int* in_sizes, int n_in,
                              void* d_out, int out_size) {
    const float* x            = (const float*)d_in[0];
    const int*   root_nodes   = (const int*)  d_in[1];
    const float* root_biases  = (const float*)d_in[2];
    const int*   tree_indices = (const int*)  d_in[3];
    const int*   nodes_flat   = (const int*)  d_in[4];
    const float* biases_flat  = (const float*)d_in[5];
    const float4* leaf        = (const float4*)d_in[6];
    float4* out               = (float4*)d_out;

    const int B = in_sizes[0] / N_FEATS;   // 16384

    cudaFuncSetAttribute(tree_kernel,
                         cudaFuncAttributePreferredSharedMemoryCarveout, 100);

    pack_kernel<<<(TOTAL_NODES + TPB - 1) / TPB, TPB>>>(nodes_flat, biases_flat);

    dim3 grid(B / SAMPLES_PER_CTA, HALVES);
    tree_kernel<<<grid, TPB>>>(x, root_nodes, root_biases, tree_indices, leaf, B);

    reduce_kernel<<<(B + TPB - 1) / TPB, TPB>>>(out, B);
}

// round 5
// speedup vs baseline: 1.0496x; 1.0262x over previous
#include <cuda_runtime.h>
#include <cuda_fp16.h>

// Problem constants (fixed by the dataset): B=16384, F=256, T=512, D=7, C=4
#define N_FEATS     256
#define N_TREES     512
#define DEPTH       7
#define TOTAL_NODES 130048      // T * (2^(D+1) - 2)
#define N_LEAVES    131072      // T * 2^(D+1)
#define MAX_B       16384

#define TPB             256
#define WARPS_PER_CTA   8
#define SAMPLES_PER_CTA 32
#define HALVES          2
#define TREES_PER_HALF  (N_TREES / HALVES)                 // 256
#define TREES_PER_WARP  (TREES_PER_HALF / WARPS_PER_CTA)   // 32 == warp size
#define NT              8        // concurrent tree traversals per thread (ILP)

// Fused (feature_id, bias) table: one LDG.64 per level instead of two LDG.32.
__device__ int2 g_combined[TOTAL_NODES];
// Leaf table converted to half4 (8B per leaf instead of 16B).
// Value-only compression: decisions unchanged, rel_err ~2e-4 (threshold 1e-3).
__device__ uint2 g_leaf_h[N_LEAVES];
// Per-half partial sums (float4 per sample).
__device__ float4 g_part[HALVES * MAX_B];

// Fused prep: pack nodes+biases AND convert leaves fp32->fp16.
// Blocks [0, 512): leaf conversion (512*256 = 131072 = N_LEAVES exactly).
// Blocks [512, 1020): node packing (508*256 = 130048 = TOTAL_NODES exactly).
__global__ __launch_bounds__(TPB) void prep_kernel(
    const int*    __restrict__ nodes,
    const float*  __restrict__ biases,
    const float4* __restrict__ leaf)
{
    const int blk = blockIdx.x;
    const int tid = threadIdx.x;
    if (blk < 512) {
        int i = blk * TPB + tid;
        float4 v = __ldg(&leaf[i]);
        __half2 lo = __float22half2_rn(make_float2(v.x, v.y));
        __half2 hi = __float22half2_rn(make_float2(v.z, v.w));
        uint2 p;
        p.x = *reinterpret_cast<unsigned*>(&lo);
        p.y = *reinterpret_cast<unsigned*>(&hi);
        g_leaf_h[i] = p;
    } else {
        int i = (blk - 512) * TPB + tid;
        if (i < TOTAL_NODES)
            g_combined[i] = make_int2(nodes[i], __float_as_int(biases[i]));
    }
}

__global__ __launch_bounds__(TPB) void tree_kernel(
    const float*  __restrict__ x,            // (B, 256) row-major
    const int*    __restrict__ root_nodes,   // (T,)
    const float*  __restrict__ root_biases,  // (T,)
    const int*    __restrict__ tree_indices, // (T,) = 2*t
    int B)
{
    // Feature-major x tile: xs[f*32 + local_sample]. Bank = local_sample
    // => conflict-free LDS for arbitrary per-lane feature indices.
    // Reused as the cross-warp reduction buffer after traversal.
    __shared__ float xs[N_FEATS * SAMPLES_PER_CTA];   // 32 KB
    __shared__ float tmp[SAMPLES_PER_CTA][33];        // 4.2 KB transpose tile

    const int tid  = threadIdx.x;
    const int lane = tid & 31;
    const int w    = tid >> 5;
    const int s0   = blockIdx.x * SAMPLES_PER_CTA;
    const int half = blockIdx.y;

    // ---- In-CTA transpose staging: row-major gmem -> feature-major smem ----
    {
        const int cA = tid & 31;       // feature within chunk (phase A)
        const int rA = tid >> 5;       // sample row base (phase A)
        #pragma unroll
        for (int cf = 0; cf < N_FEATS; cf += 32) {
            #pragma unroll
            for (int k = 0; k < 4; k++) {
                int r = rA + k * 8;
                tmp[r][cA] = x[(s0 + r) * N_FEATS + cf + cA];
            }
            __syncthreads();
            #pragma unroll
            for (int k = 0; k < 4; k++) {
                int c = w + k * 8;
                xs[(cf + c) * 32 + lane] = tmp[lane][c];
            }
            __syncthreads();
        }
    }

    float a0 = 0.f, a1 = 0.f, a2 = 0.f, a3 = 0.f;
    const int tbase = half * TREES_PER_HALF + w * TREES_PER_WARP;

    // Per-warp root metadata: one tree per lane, broadcast later via shfl.
    const int   rn_l = __ldg(&root_nodes[tbase + lane]);
    const float rb_l = __ldg(&root_biases[tbase + lane]);
    const int   ti_l = __ldg(&tree_indices[tbase + lane]);

    for (int tt = 0; tt < TREES_PER_WARP; tt += NT) {
        int idx[NT];

        // Root level: per-tree metadata broadcast from lane registers.
        #pragma unroll
        for (int j = 0; j < NT; j++) {
            int   rf = __shfl_sync(0xffffffffu, rn_l, tt + j);
            float rb = __shfl_sync(0xffffffffu, rb_l, tt + j);
            int   ti = __shfl_sync(0xffffffffu, ti_l, tt + j);
            idx[j] = ti + (xs[rf * 32 + lane] < rb ? 1 : 0);
        }

        // Levels 1..7: level-l block starts at T*(2^l - 2); idx is GLOBAL
        // within the level (matches reference).
        int off = 0;
        #pragma unroll
        for (int l = 1; l <= DEPTH; l++) {
            #pragma unroll
            for (int j = 0; j < NT; j++) {
                int2 e = __ldg(&g_combined[off + idx[j]]);        // LDG.64
                float f = xs[e.x * 32 + lane];                    // LDS, no conflicts
                idx[j] = 2 * idx[j] + (f < __int_as_float(e.y) ? 1 : 0);
            }
            off += N_TREES << l;
        }

        // Leaf accumulate: one LDG.64 (half4) per tree, fp32 accumulation.
        #pragma unroll
        for (int j = 0; j < NT; j++) {
            uint2 p = __ldg(&g_leaf_h[idx[j]]);
            float2 lo = __half22float2(*reinterpret_cast<__half2*>(&p.x));
            float2 hi = __half22float2(*reinterpret_cast<__half2*>(&p.y));
            a0 += lo.x; a1 += lo.y; a2 += hi.x; a3 += hi.y;
        }
    }

    // Deterministic cross-warp reduction, reusing xs as scratch.
    __syncthreads();                       // all warps done reading xs
    float* red = xs;                       // [warp][lane][4]
    red[(w * SAMPLES_PER_CTA + lane) * 4 + 0] = a0;
    red[(w * SAMPLES_PER_CTA + lane) * 4 + 1] = a1;
    red[(w * SAMPLES_PER_CTA + lane) * 4 + 2] = a2;
    red[(w * SAMPLES_PER_CTA + lane) * 4 + 3] = a3;
    __syncthreads();

    if (w == 0) {
        float4 r = make_float4(0.f, 0.f, 0.f, 0.f);
        #pragma unroll
        for (int ww = 0; ww < WARPS_PER_CTA; ww++) {
            const float* p = red + (ww * SAMPLES_PER_CTA + lane) * 4;
            r.x += p[0]; r.y += p[1]; r.z += p[2]; r.w += p[3];
        }
        g_part[half * B + s0 + lane] = r;
    }
}

__global__ void reduce_kernel(float4* __restrict__ out, int B) {
    int i = blockIdx.x * blockDim.x + threadIdx.x;
    if (i < B) {
        float4 a = g_part[i];
        float4 b = g_part[B + i];
        out[i] = make_float4(a.x + b.x, a.y + b.y, a.z + b.z, a.w + b.w);
    }
}

extern "C" void kernel_launch(void* const* d_in, const int* in_sizes, int n_in,
                              void* d_out, int out_size) {
    const float* x            = (const float*)d_in[0];
    const int*   root_nodes   = (const int*)  d_in[1];
    const float* root_biases  = (const float*)d_in[2];
    const int*   tree_indices = (const int*)  d_in[3];
    const int*   nodes_flat   = (const int*)  d_in[4];
    const float* biases_flat  = (const float*)d_in[5];
    const float4* leaf        = (const float4*)d_in[6];
    float4* out               = (float4*)d_out;

    const int B = in_sizes[0] / N_FEATS;   // 16384

    cudaFuncSetAttribute(tree_kernel,
                         cudaFuncAttributePreferredSharedMemoryCarveout, 100);

    prep_kernel<<<1020, TPB>>>(nodes_flat, biases_flat, leaf);

    dim3 grid(B / SAMPLES_PER_CTA, HALVES);
    tree_kernel<<<grid, TPB>>>(x, root_nodes, root_biases, tree_indices, B);

    reduce_kernel<<<(B + TPB - 1) / TPB, TPB>>>(out, B);
}

// round 6
// speedup vs baseline: 1.1171x; 1.0643x over previous
#include <cuda_runtime.h>
#include <cuda_fp16.h>

// Problem constants (fixed by the dataset): B=16384, F=256, T=512, D=7, C=4
#define N_FEATS     256
#define N_TREES     512
#define DEPTH       7
#define TOTAL_NODES 130048      // T * (2^(D+1) - 2)
#define N_LEAVES    131072      // T * 2^(D+1)
#define MAX_B       16384

// Level offsets: off(l) = T*(2^l - 2). Levels 1..4 occupy [0, 15360).
#define SHALLOW_NODES 15360     // 512*(2+4+8+16)
#define DEEP_NODES    114688    // 512*(32+64+128)

#define TPB             256
#define WARPS_PER_CTA   8
#define SAMPLES_PER_CTA 32
#define HALVES          2
#define TREES_PER_HALF  (N_TREES / HALVES)                 // 256
#define TREES_PER_WARP  (TREES_PER_HALF / WARPS_PER_CTA)   // 32 == warp size
#define NT              8        // concurrent tree traversals per thread (ILP)

// Levels 1-4: fused (feature, bias) int2 — block is <=1 line, packing optimal.
__device__ int2 g_packed14[SHALLOW_NODES];
// Levels 5-7: feature ids as u8 — level-7 per-tree block = 128B = ONE line.
// (bias for deep levels is read straight from biases_flat; no copy.)
__device__ unsigned char g_feat_u8[DEEP_NODES];
// Leaf table as half4 (8B). Value-only compression, rel_err ~2e-4.
__device__ uint2 g_leaf_h[N_LEAVES];
// Per-half partial sums.
__device__ float4 g_part[HALVES * MAX_B];

// Prep: 1020 blocks exactly cover the three jobs.
//  blk [0,60):    pack levels 1-4        (60*256  = 15360)
//  blk [60,508):  u8 features levels 5-7 (448*256 = 114688)
//  blk [508,1020): leaf fp32 -> fp16     (512*256 = 131072)
__global__ __launch_bounds__(TPB) void prep_kernel(
    const int*    __restrict__ nodes,
    const float*  __restrict__ biases,
    const float4* __restrict__ leaf)
{
    const int blk = blockIdx.x;
    const int tid = threadIdx.x;
    if (blk < 60) {
        int i = blk * TPB + tid;
        g_packed14[i] = make_int2(__ldg(&nodes[i]), __float_as_int(__ldg(&biases[i])));
    } else if (blk < 508) {
        int i = (blk - 60) * TPB + tid;
        g_feat_u8[i] = (unsigned char)__ldg(&nodes[SHALLOW_NODES + i]);
    } else {
        int i = (blk - 508) * TPB + tid;
        float4 v = __ldg(&leaf[i]);
        __half2 lo = __float22half2_rn(make_float2(v.x, v.y));
        __half2 hi = __float22half2_rn(make_float2(v.z, v.w));
        uint2 p;
        p.x = *reinterpret_cast<unsigned*>(&lo);
        p.y = *reinterpret_cast<unsigned*>(&hi);
        g_leaf_h[i] = p;
    }
}

__global__ __launch_bounds__(TPB) void tree_kernel(
    const float*  __restrict__ x,            // (B, 256) row-major
    const int*    __restrict__ root_nodes,   // (T,)
    const float*  __restrict__ root_biases,  // (T,)
    const int*    __restrict__ tree_indices, // (T,) = 2*t
    const float*  __restrict__ biases_flat,  // (TOTAL_NODES,) original
    int B)
{
    // Feature-major x tile: xs[f*32 + local_sample]; bank = local_sample ->
    // conflict-free LDS for arbitrary feature indices. Reused for reduction.
    __shared__ float xs[N_FEATS * SAMPLES_PER_CTA];   // 32 KB
    __shared__ float tmp[SAMPLES_PER_CTA][33];        // transpose tile

    const int tid  = threadIdx.x;
    const int lane = tid & 31;
    const int w    = tid >> 5;
    const int s0   = blockIdx.x * SAMPLES_PER_CTA;
    const int half = blockIdx.y;

    // In-CTA transpose staging: row-major gmem -> feature-major smem.
    {
        const int cA = tid & 31;
        const int rA = tid >> 5;
        #pragma unroll
        for (int cf = 0; cf < N_FEATS; cf += 32) {
            #pragma unroll
            for (int k = 0; k < 4; k++) {
                int r = rA + k * 8;
                tmp[r][cA] = x[(s0 + r) * N_FEATS + cf + cA];
            }
            __syncthreads();
            #pragma unroll
            for (int k = 0; k < 4; k++) {
                int c = w + k * 8;
                xs[(cf + c) * 32 + lane] = tmp[lane][c];
            }
            __syncthreads();
        }
    }

    float a0 = 0.f, a1 = 0.f, a2 = 0.f, a3 = 0.f;
    const int tbase = half * TREES_PER_HALF + w * TREES_PER_WARP;

    // Per-warp root metadata: one tree per lane, broadcast via shfl.
    const int   rn_l = __ldg(&root_nodes[tbase + lane]);
    const float rb_l = __ldg(&root_biases[tbase + lane]);
    const int   ti_l = __ldg(&tree_indices[tbase + lane]);

    for (int tt = 0; tt < TREES_PER_WARP; tt += NT) {
        int idx[NT];

        #pragma unroll
        for (int j = 0; j < NT; j++) {
            int   rf = __shfl_sync(0xffffffffu, rn_l, tt + j);
            float rb = __shfl_sync(0xffffffffu, rb_l, tt + j);
            int   ti = __shfl_sync(0xffffffffu, ti_l, tt + j);
            idx[j] = ti + (xs[rf * 32 + lane] < rb ? 1 : 0);
        }

        // Levels 1..7 (level-l block starts at T*(2^l - 2); idx is GLOBAL).
        int off = 0;
        #pragma unroll
        for (int l = 1; l <= DEPTH; l++) {
            if (l <= 4) {
                // Packed int2: whole level block <= 1 cache line per tree.
                #pragma unroll
                for (int j = 0; j < NT; j++) {
                    int2 e = __ldg(&g_packed14[off + idx[j]]);
                    float f = xs[e.x * 32 + lane];
                    idx[j] = 2 * idx[j] + (f < __int_as_float(e.y) ? 1 : 0);
                }
            } else {
                // Split: u8 feature (1-line block) + f32 bias from original.
                #pragma unroll
                for (int j = 0; j < NT; j++) {
                    int g = off + idx[j];
                    int fe = (int)__ldg(&g_feat_u8[g - SHALLOW_NODES]);
                    float b = __ldg(&biases_flat[g]);
                    float f = xs[fe * 32 + lane];
                    idx[j] = 2 * idx[j] + (f < b ? 1 : 0);
                }
            }
            off += N_TREES << l;
        }

        // Leaf accumulate: one LDG.64 (half4) per tree, fp32 accumulation.
        #pragma unroll
        for (int j = 0; j < NT; j++) {
            uint2 p = __ldg(&g_leaf_h[idx[j]]);
            float2 lo = __half22float2(*reinterpret_cast<__half2*>(&p.x));
            float2 hi = __half22float2(*reinterpret_cast<__half2*>(&p.y));
            a0 += lo.x; a1 += lo.y; a2 += hi.x; a3 += hi.y;
        }
    }

    // Deterministic cross-warp reduction, reusing xs as scratch.
    __syncthreads();
    float* red = xs;
    red[(w * SAMPLES_PER_CTA + lane) * 4 + 0] = a0;
    red[(w * SAMPLES_PER_CTA + lane) * 4 + 1] = a1;
    red[(w * SAMPLES_PER_CTA + lane) * 4 + 2] = a2;
    red[(w * SAMPLES_PER_CTA + lane) * 4 + 3] = a3;
    __syncthreads();

    if (w == 0) {
        float4 r = make_float4(0.f, 0.f, 0.f, 0.f);
        #pragma unroll
        for (int ww = 0; ww < WARPS_PER_CTA; ww++) {
            const float* p = red + (ww * SAMPLES_PER_CTA + lane) * 4;
            r.x += p[0]; r.y += p[1]; r.z += p[2]; r.w += p[3];
        }
        g_part[half * B + s0 + lane] = r;
    }
}

__global__ void reduce_kernel(float4* __restrict__ out, int B) {
    int i = blockIdx.x * blockDim.x + threadIdx.x;
    if (i < B) {
        float4 a = g_part[i];
        float4 b = g_part[B + i];
        out[i] = make_float4(a.x + b.x, a.y + b.y, a.z + b.z, a.w + b.w);
    }
}

extern "C" void kernel_launch(void* const* d_in, const int* in_sizes, int n_in,
                              void* d_out, int out_size) {
    const float* x            = (const float*)d_in[0];
    const int*   root_nodes   = (const int*)  d_in[1];
    const float* root_biases  = (const float*)d_in[2];
    const int*   tree_indices = (const int*)  d_in[3];
    const int*   nodes_flat   = (const int*)  d_in[4];
    const float* biases_flat  = (const float*)d_in[5];
    const float4* leaf        = (const float4*)d_in[6];
    float4* out               = (float4*)d_out;

    const int B = in_sizes[0] / N_FEATS;   // 16384

    cudaFuncSetAttribute(tree_kernel,
                         cudaFuncAttributePreferredSharedMemoryCarveout, 100);

    prep_kernel<<<1020, TPB>>>(nodes_flat, biases_flat, leaf);

    dim3 grid(B / SAMPLES_PER_CTA, HALVES);
    tree_kernel<<<grid, TPB>>>(x, root_nodes, root_biases, tree_indices,
                               biases_flat, B);

    reduce_kernel<<<(B + TPB - 1) / TPB, TPB>>>(out, B);
}